// round 13
// baseline (speedup 1.0000x reference)
#include <cuda_runtime.h>
#include <math.h>

#define VOCAB 32000
#define EMB 128
#define HID 128
#define NLAB 9
#define BATCH 128
#define SEQ 1024
#define NTOK (BATCH * SEQ)
#define BLK 16                     // xw staging block (steps per LDG batch)
#define NBLK (SEQ / BLK)

// Scratch (static device arrays: allocation-free, overwrite-only => graph-replay safe)
__device__ float g_T[VOCAB * HID];              // emb_table @ Wx + b_h   (16.4 MB)
__device__ float g_hidden[(size_t)NTOK * HID];  // hidden states (64 MB, streaming)
__device__ float g_partial[512];                // per-CTA loss partials

// ---- packed f32x2 helpers (Blackwell FFMA2) ----
__device__ __forceinline__ unsigned long long pack2(float lo, float hi) {
    unsigned long long r;
    asm("mov.b64 %0, {%1, %2};" : "=l"(r) : "f"(lo), "f"(hi));
    return r;
}
__device__ __forceinline__ unsigned long long fma2(unsigned long long a,
                                                   unsigned long long b,
                                                   unsigned long long c) {
    unsigned long long d;
    asm("fma.rn.f32x2 %0, %1, %2, %3;" : "=l"(d) : "l"(a), "l"(b), "l"(c));
    return d;
}
__device__ __forceinline__ unsigned long long add2(unsigned long long a,
                                                   unsigned long long b) {
    unsigned long long d;
    asm("add.rn.f32x2 %0, %1, %2;" : "=l"(d) : "l"(a), "l"(b));
    return d;
}
__device__ __forceinline__ float sum2(unsigned long long v) {
    float lo, hi;
    asm("mov.b64 {%0, %1}, %2;" : "=f"(lo), "=f"(hi) : "l"(v));
    return lo + hi;
}
__device__ __forceinline__ float tanh_fast(float x) {
    float r;
    asm("tanh.approx.f32 %0, %1;" : "=f"(r) : "f"(x));
    return r;
}
__device__ __forceinline__ void stg_stream(float* p, float v) {
    asm volatile("st.global.cs.f32 [%0], %1;" :: "l"(p), "f"(v));
}
__device__ __forceinline__ void bar_named(int id) {
    asm volatile("bar.sync %0, 128;" :: "r"(id) : "memory");
}

// no-op kernels: shift ncu's captured launch index (-s 5 -c 1) onto k_scan
__global__ void k_nop() {}

// ---------------------------------------------------------------------------
// Kernel 1: T[v][j] = sum_e emb[v][e] * Wx[e][j] + b_h[j]
// ---------------------------------------------------------------------------
__global__ void __launch_bounds__(128) k_precompute(const float* __restrict__ emb,
                                                    const float* __restrict__ W_h,
                                                    const float* __restrict__ b_h) {
    const int j = threadIdx.x;
    unsigned long long wx2[EMB / 2];
#pragma unroll
    for (int e = 0; e < EMB / 2; e++)
        wx2[e] = pack2(W_h[(2 * e) * HID + j], W_h[(2 * e + 1) * HID + j]);
    const float bj = b_h[j];

    __shared__ __align__(16) float es[2][EMB];
    const int row0 = blockIdx.x * 128;

    es[0][j] = emb[(size_t)row0 * EMB + j];
    __syncthreads();

    for (int r = 0; r < 128; r++) {
        const int buf = r & 1;
        const int row = row0 + r;
        if (r + 1 < 128) es[buf ^ 1][j] = emb[(size_t)(row + 1) * EMB + j];

        const ulonglong2* e8 = (const ulonglong2*)es[buf];
        unsigned long long a0 = pack2(bj, 0.f), a1 = 0ull, a2 = 0ull, a3 = 0ull;
#pragma unroll
        for (int k = 0; k < EMB / 4; k++) {
            ulonglong2 v = e8[k];
            if ((k & 1) == 0) { a0 = fma2(v.x, wx2[2 * k], a0); a1 = fma2(v.y, wx2[2 * k + 1], a1); }
            else              { a2 = fma2(v.x, wx2[2 * k], a2); a3 = fma2(v.y, wx2[2 * k + 1], a3); }
        }
        g_T[row * HID + j] = sum2(add2(add2(a0, a1), add2(a2, a3)));
        __syncthreads();
    }
}

// ---------------------------------------------------------------------------
// Kernel 2: sequential scan. EXACT R9 per-row structure (SMEM staging
// firewall, BLK=16, 4 accumulators, xw via LDS at step head, burst drained
// once per block, stores post-barrier).
// SINGLE CHANGE vs R9: TWO independent rows per CTA (256 threads), warps 0-3
// row A / 4-7 row B -> 2 warps per SMSP. Inner loop is LDG-free (firewall),
// so the co-resident warp fills the short LDS/FMA/tanh/BAR latencies.
// Per-row named barriers keep the rows decoupled.
// ---------------------------------------------------------------------------
__global__ void __launch_bounds__(256) k_scan(const int* __restrict__ ids,
                                              const float* __restrict__ W_h) {
    const int tid = threadIdx.x;
    const int r = tid >> 7;            // row within CTA (0/1)
    const int j = tid & 127;           // hidden column
    const int b = blockIdx.x * 2 + r;  // global batch row
    const int barid = r + 1;

    unsigned long long wh2[HID / 2];
#pragma unroll
    for (int k = 0; k < HID / 2; k++)
        wh2[k] = pack2(W_h[(EMB + 2 * k) * HID + j], W_h[(EMB + 2 * k + 1) * HID + j]);

    __shared__ __align__(16) float hs[2][2][HID];          // [row][buf][col]
    __shared__ float xw_sm[2][2][BLK][HID];                // [row][dbuf][u][col]
    __shared__ int ids_sh[2][SEQ];
    const int* idrow = ids + b * SEQ;
#pragma unroll
    for (int t = j; t < SEQ; t += 128) ids_sh[r][t] = idrow[t];
    hs[r][0][j] = 0.f;
    __syncthreads();

    // prologue: stage block 0
    {
        float xr[BLK];
#pragma unroll
        for (int u = 0; u < BLK; u++) xr[u] = __ldg(g_T + ids_sh[r][u] * HID + j);
#pragma unroll
        for (int u = 0; u < BLK; u++) xw_sm[r][0][u][j] = xr[u];
    }
    bar_named(barid);

    float* hout = g_hidden + (size_t)b * SEQ * HID + j;
    float prev = 0.f;
    float xr[BLK];

    for (int blk = 0; blk < NBLK; blk++) {
        const int cur = blk & 1;
        // issue next block's gathers NOW; they complete during the 16 steps below
        const int nbase = (blk + 1 < NBLK) ? (blk + 1) * BLK : blk * BLK;
#pragma unroll
        for (int u = 0; u < BLK; u++) xr[u] = __ldg(g_T + ids_sh[r][nbase + u] * HID + j);

#pragma unroll
        for (int u = 0; u < BLK; u++) {
            const int t = blk * BLK + u;
            const float xw = xw_sm[r][cur][u][j];        // LDS, no LDG alias

            const int buf = t & 1;
            const ulonglong2* h8 = (const ulonglong2*)hs[r][buf];
            unsigned long long a0 = pack2(xw, 0.f), a1 = 0ull, a2 = 0ull, a3 = 0ull;
#pragma unroll
            for (int k = 0; k < HID / 4; k++) {
                ulonglong2 v = h8[k];
                if ((k & 1) == 0) { a0 = fma2(v.x, wh2[2 * k], a0); a1 = fma2(v.y, wh2[2 * k + 1], a1); }
                else              { a2 = fma2(v.x, wh2[2 * k], a2); a3 = fma2(v.y, wh2[2 * k + 1], a3); }
            }
            const float hv = tanh_fast(sum2(add2(add2(a0, a1), add2(a2, a3))));
            hs[r][buf ^ 1][j] = hv;

            if (u == BLK - 1) {
                // drain the block's LDGs ONCE, right before the barrier
#pragma unroll
                for (int v2 = 0; v2 < BLK; v2++) xw_sm[r][cur ^ 1][v2][j] = xr[v2];
            }
            bar_named(barid);
            // store previous h AFTER the barrier: overlaps next step's compute
            if (t) stg_stream(hout + (size_t)(t - 1) * HID, prev);
            prev = hv;
        }
    }
    stg_stream(hout + (size_t)(SEQ - 1) * HID, prev);
}

// ---------------------------------------------------------------------------
// Kernel 3: logits + per-token NLL. One warp per token (strided).
// ---------------------------------------------------------------------------
__global__ void __launch_bounds__(256) k_logits(const int* __restrict__ labels,
                                                const float* __restrict__ W_out,
                                                const float* __restrict__ b_out,
                                                float* __restrict__ out_logits) {
    __shared__ float Wsh[HID * NLAB];
    __shared__ float bsh[NLAB];
    __shared__ float wsum[8];
    const int tid = threadIdx.x;
    for (int i = tid; i < HID * NLAB; i += blockDim.x) Wsh[i] = W_out[i];
    if (tid < NLAB) bsh[tid] = b_out[tid];
    __syncthreads();

    const int lane = tid & 31, warp = tid >> 5;
    const int gwarp = blockIdx.x * (blockDim.x >> 5) + warp;
    const int nwarp = gridDim.x * (blockDim.x >> 5);
    float lsum = 0.f;

    for (int tok = gwarp; tok < NTOK; tok += nwarp) {
        const float* h = g_hidden + (size_t)tok * HID;
        const float h0 = __ldcs(h + lane), h1 = __ldcs(h + lane + 32),
                    h2 = __ldcs(h + lane + 64), h3 = __ldcs(h + lane + 96);
        float lg[NLAB];
#pragma unroll
        for (int l = 0; l < NLAB; l++) {
            float p = h0 * Wsh[lane * NLAB + l]
                    + h1 * Wsh[(lane + 32) * NLAB + l]
                    + h2 * Wsh[(lane + 64) * NLAB + l]
                    + h3 * Wsh[(lane + 96) * NLAB + l];
#pragma unroll
            for (int off = 16; off; off >>= 1) p += __shfl_xor_sync(0xffffffffu, p, off);
            lg[l] = p + bsh[l];
        }
        if (lane < NLAB) stg_stream(out_logits + (size_t)tok * NLAB + lane, lg[lane]);
        if (lane == 0) {
            float m = lg[0];
#pragma unroll
            for (int l = 1; l < NLAB; l++) m = fmaxf(m, lg[l]);
            float s = 0.f;
#pragma unroll
            for (int l = 0; l < NLAB; l++) s += expf(lg[l] - m);
            const float lse = m + logf(s);
            lsum += lse - lg[labels[tok]];
        }
    }
    if (lane == 0) wsum[warp] = lsum;
    __syncthreads();
    if (tid == 0) {
        float s = 0.f;
#pragma unroll
        for (int w = 0; w < 8; w++) s += wsum[w];
        g_partial[blockIdx.x] = s;  // overwrite, replay-safe
    }
}

// ---------------------------------------------------------------------------
// Kernel 4: reduce partials -> loss scalar
// ---------------------------------------------------------------------------
__global__ void __launch_bounds__(256) k_loss(float* __restrict__ out_loss, int nblocks) {
    __shared__ float s[256];
    float v = 0.f;
    for (int i = threadIdx.x; i < nblocks; i += 256) v += g_partial[i];
    s[threadIdx.x] = v;
    __syncthreads();
    for (int st = 128; st; st >>= 1) {
        if (threadIdx.x < st) s[threadIdx.x] += s[threadIdx.x + st];
        __syncthreads();
    }
    if (threadIdx.x == 0) out_loss[0] = s[0] / (float)NTOK;
}

extern "C" void kernel_launch(void* const* d_in, const int* in_sizes, int n_in,
                              void* d_out, int out_size) {
    const int*   input_ids = (const int*)d_in[0];
    const int*   labels    = (const int*)d_in[3];
    const float* emb_table = (const float*)d_in[4];
    const float* W_h       = (const float*)d_in[5];
    const float* b_h       = (const float*)d_in[6];
    const float* W_out     = (const float*)d_in[7];
    const float* b_out     = (const float*)d_in[8];
    float* out = (float*)d_out;

    // two no-ops so ncu's captured launch (#6, incl. 2 harness launches) = k_scan
    k_nop<<<1, 32>>>();
    k_nop<<<1, 32>>>();
    k_precompute<<<VOCAB / 128, 128>>>(emb_table, W_h, b_h);
    k_scan<<<BATCH / 2, 256>>>(input_ids, W_h);
    k_logits<<<256, 256>>>(labels, W_out, b_out, out);
    k_loss<<<1, 256>>>(out + (out_size - 1), 256);
}

// round 14
// speedup vs baseline: 2.3617x; 2.3617x over previous
#include <cuda_runtime.h>
#include <math.h>

#define VOCAB 32000
#define EMB 128
#define HID 128
#define NLAB 9
#define BATCH 128
#define SEQ 1024
#define NTOK (BATCH * SEQ)
#define BLK 16                     // scan: xw staging block (steps per LDG batch)
#define NBLK (SEQ / BLK)
#define PBURST 8                   // precompute: emb rows staged per barrier

// Scratch (static device arrays: allocation-free, overwrite-only => graph-replay safe)
__device__ float g_T[VOCAB * HID];              // emb_table @ Wx + b_h   (16.4 MB)
__device__ float g_hidden[(size_t)NTOK * HID];  // hidden states (64 MB, streaming)
__device__ float g_partial[512];                // per-CTA loss partials

// ---- packed f32x2 helpers (Blackwell FFMA2) ----
__device__ __forceinline__ unsigned long long pack2(float lo, float hi) {
    unsigned long long r;
    asm("mov.b64 %0, {%1, %2};" : "=l"(r) : "f"(lo), "f"(hi));
    return r;
}
__device__ __forceinline__ unsigned long long fma2(unsigned long long a,
                                                   unsigned long long b,
                                                   unsigned long long c) {
    unsigned long long d;
    asm("fma.rn.f32x2 %0, %1, %2, %3;" : "=l"(d) : "l"(a), "l"(b), "l"(c));
    return d;
}
__device__ __forceinline__ unsigned long long add2(unsigned long long a,
                                                   unsigned long long b) {
    unsigned long long d;
    asm("add.rn.f32x2 %0, %1, %2;" : "=l"(d) : "l"(a), "l"(b));
    return d;
}
__device__ __forceinline__ float sum2(unsigned long long v) {
    float lo, hi;
    asm("mov.b64 {%0, %1}, %2;" : "=f"(lo), "=f"(hi) : "l"(v));
    return lo + hi;
}
__device__ __forceinline__ float tanh_fast(float x) {
    float r;
    asm("tanh.approx.f32 %0, %1;" : "=f"(r) : "f"(x));
    return r;
}
__device__ __forceinline__ void stg_stream(float* p, float v) {
    asm volatile("st.global.cs.f32 [%0], %1;" :: "l"(p), "f"(v));
}

// no-op kernels: shift ncu's captured launch index (-s 5 -c 1) onto k_precompute
__global__ void k_nop() {}

// ---------------------------------------------------------------------------
// Kernel 1: T[v][j] = sum_e emb[v][e] * Wx[e][j] + b_h[j]
// R14 FIX: the old version drained a DRAM-latency LDG->STS at EVERY row's
// barrier (~650cyc/row). Now 8 rows are staged per barrier, firewall-style:
// burst 8 LDGs to registers, compute 8 rows from the current buffer, drain
// the burst once, one __syncthreads per 8 rows.
// ---------------------------------------------------------------------------
__global__ void __launch_bounds__(128) k_precompute(const float* __restrict__ emb,
                                                    const float* __restrict__ W_h,
                                                    const float* __restrict__ b_h) {
    const int j = threadIdx.x;
    unsigned long long wx2[EMB / 2];
#pragma unroll
    for (int e = 0; e < EMB / 2; e++)
        wx2[e] = pack2(W_h[(2 * e) * HID + j], W_h[(2 * e + 1) * HID + j]);
    const float bj = b_h[j];

    __shared__ __align__(16) float es[2][PBURST][EMB];
    const int row0 = blockIdx.x * 128;

    // prologue: stage rows 0..7
    {
        float er[PBURST];
#pragma unroll
        for (int u = 0; u < PBURST; u++) er[u] = __ldg(emb + (size_t)(row0 + u) * EMB + j);
#pragma unroll
        for (int u = 0; u < PBURST; u++) es[0][u][j] = er[u];
    }
    __syncthreads();

    const int nblocks = 128 / PBURST;
    for (int blk = 0; blk < nblocks; blk++) {
        const int cur = blk & 1;
        // burst next 8 rows into registers (waited once, at the drain below)
        const int nb = (blk + 1 < nblocks) ? (blk + 1) * PBURST : blk * PBURST;
        float er[PBURST];
#pragma unroll
        for (int u = 0; u < PBURST; u++) er[u] = __ldg(emb + (size_t)(row0 + nb + u) * EMB + j);

#pragma unroll
        for (int u = 0; u < PBURST; u++) {
            const int row = row0 + blk * PBURST + u;
            const ulonglong2* e8 = (const ulonglong2*)es[cur][u];
            unsigned long long a0 = pack2(bj, 0.f), a1 = 0ull, a2 = 0ull, a3 = 0ull;
#pragma unroll
            for (int k = 0; k < EMB / 4; k++) {
                ulonglong2 v = e8[k];
                if ((k & 1) == 0) { a0 = fma2(v.x, wx2[2 * k], a0); a1 = fma2(v.y, wx2[2 * k + 1], a1); }
                else              { a2 = fma2(v.x, wx2[2 * k], a2); a3 = fma2(v.y, wx2[2 * k + 1], a3); }
            }
            g_T[row * HID + j] = sum2(add2(add2(a0, a1), add2(a2, a3)));
        }
        // drain the burst once per 8 rows
#pragma unroll
        for (int u = 0; u < PBURST; u++) es[cur ^ 1][u][j] = er[u];
        __syncthreads();
    }
}

// ---------------------------------------------------------------------------
// Kernel 2: sequential scan — EXACT R9 structure (best measured: 215us).
// 128 threads, 1 row/CTA, grid=128; SMEM staging firewall, BLK=16,
// 4 accumulators, stores post-barrier.
// ---------------------------------------------------------------------------
__global__ void __launch_bounds__(128) k_scan(const int* __restrict__ ids,
                                              const float* __restrict__ W_h) {
    const int b = blockIdx.x;
    const int j = threadIdx.x;

    unsigned long long wh2[HID / 2];
#pragma unroll
    for (int k = 0; k < HID / 2; k++)
        wh2[k] = pack2(W_h[(EMB + 2 * k) * HID + j], W_h[(EMB + 2 * k + 1) * HID + j]);

    __shared__ __align__(16) float hs[2][HID];
    __shared__ float xw_sm[2][BLK][HID];   // double-buffered staged gather
    __shared__ int ids_sh[SEQ];
    const int* idrow = ids + b * SEQ;
#pragma unroll
    for (int t = j; t < SEQ; t += 128) ids_sh[t] = idrow[t];
    hs[0][j] = 0.f;
    __syncthreads();

    // prologue: stage block 0
    {
        float xr[BLK];
#pragma unroll
        for (int u = 0; u < BLK; u++) xr[u] = __ldg(g_T + ids_sh[u] * HID + j);
#pragma unroll
        for (int u = 0; u < BLK; u++) xw_sm[0][u][j] = xr[u];
    }
    __syncthreads();

    float* hout = g_hidden + (size_t)b * SEQ * HID + j;
    float prev = 0.f;
    float xr[BLK];

    for (int blk = 0; blk < NBLK; blk++) {
        const int cur = blk & 1;
        // issue next block's gathers NOW; they complete during the 16 steps below
        const int nbase = (blk + 1 < NBLK) ? (blk + 1) * BLK : blk * BLK;
#pragma unroll
        for (int u = 0; u < BLK; u++) xr[u] = __ldg(g_T + ids_sh[nbase + u] * HID + j);

#pragma unroll
        for (int u = 0; u < BLK; u++) {
            const int t = blk * BLK + u;
            const float xw = xw_sm[cur][u][j];          // LDS, 29cyc, no LDG alias

            const int buf = t & 1;
            const ulonglong2* h8 = (const ulonglong2*)hs[buf];
            unsigned long long a0 = pack2(xw, 0.f), a1 = 0ull, a2 = 0ull, a3 = 0ull;
#pragma unroll
            for (int k = 0; k < HID / 4; k++) {
                ulonglong2 v = h8[k];
                if ((k & 1) == 0) { a0 = fma2(v.x, wh2[2 * k], a0); a1 = fma2(v.y, wh2[2 * k + 1], a1); }
                else              { a2 = fma2(v.x, wh2[2 * k], a2); a3 = fma2(v.y, wh2[2 * k + 1], a3); }
            }
            const float hv = tanh_fast(sum2(add2(add2(a0, a1), add2(a2, a3))));
            hs[buf ^ 1][j] = hv;

            if (u == BLK - 1) {
                // drain the block's LDGs ONCE, right before the barrier
#pragma unroll
                for (int v2 = 0; v2 < BLK; v2++) xw_sm[cur ^ 1][v2][j] = xr[v2];
            }
            __syncthreads();
            // store previous h AFTER the barrier: overlaps next step's compute
            if (t) stg_stream(hout + (size_t)(t - 1) * HID, prev);
            prev = hv;
        }
    }
    stg_stream(hout + (size_t)(SEQ - 1) * HID, prev);
}

// ---------------------------------------------------------------------------
// Kernel 3: logits + per-token NLL. One warp per token (strided).
// ---------------------------------------------------------------------------
__global__ void __launch_bounds__(256) k_logits(const int* __restrict__ labels,
                                                const float* __restrict__ W_out,
                                                const float* __restrict__ b_out,
                                                float* __restrict__ out_logits) {
    __shared__ float Wsh[HID * NLAB];
    __shared__ float bsh[NLAB];
    __shared__ float wsum[8];
    const int tid = threadIdx.x;
    for (int i = tid; i < HID * NLAB; i += blockDim.x) Wsh[i] = W_out[i];
    if (tid < NLAB) bsh[tid] = b_out[tid];
    __syncthreads();

    const int lane = tid & 31, warp = tid >> 5;
    const int gwarp = blockIdx.x * (blockDim.x >> 5) + warp;
    const int nwarp = gridDim.x * (blockDim.x >> 5);
    float lsum = 0.f;

    for (int tok = gwarp; tok < NTOK; tok += nwarp) {
        const float* h = g_hidden + (size_t)tok * HID;
        const float h0 = __ldcs(h + lane), h1 = __ldcs(h + lane + 32),
                    h2 = __ldcs(h + lane + 64), h3 = __ldcs(h + lane + 96);
        float lg[NLAB];
#pragma unroll
        for (int l = 0; l < NLAB; l++) {
            float p = h0 * Wsh[lane * NLAB + l]
                    + h1 * Wsh[(lane + 32) * NLAB + l]
                    + h2 * Wsh[(lane + 64) * NLAB + l]
                    + h3 * Wsh[(lane + 96) * NLAB + l];
#pragma unroll
            for (int off = 16; off; off >>= 1) p += __shfl_xor_sync(0xffffffffu, p, off);
            lg[l] = p + bsh[l];
        }
        if (lane < NLAB) stg_stream(out_logits + (size_t)tok * NLAB + lane, lg[lane]);
        if (lane == 0) {
            float m = lg[0];
#pragma unroll
            for (int l = 1; l < NLAB; l++) m = fmaxf(m, lg[l]);
            float s = 0.f;
#pragma unroll
            for (int l = 0; l < NLAB; l++) s += expf(lg[l] - m);
            const float lse = m + logf(s);
            lsum += lse - lg[labels[tok]];
        }
    }
    if (lane == 0) wsum[warp] = lsum;
    __syncthreads();
    if (tid == 0) {
        float s = 0.f;
#pragma unroll
        for (int w = 0; w < 8; w++) s += wsum[w];
        g_partial[blockIdx.x] = s;  // overwrite, replay-safe
    }
}

// ---------------------------------------------------------------------------
// Kernel 4: reduce partials -> loss scalar
// ---------------------------------------------------------------------------
__global__ void __launch_bounds__(256) k_loss(float* __restrict__ out_loss, int nblocks) {
    __shared__ float s[256];
    float v = 0.f;
    for (int i = threadIdx.x; i < nblocks; i += 256) v += g_partial[i];
    s[threadIdx.x] = v;
    __syncthreads();
    for (int st = 128; st; st >>= 1) {
        if (threadIdx.x < st) s[threadIdx.x] += s[threadIdx.x + st];
        __syncthreads();
    }
    if (threadIdx.x == 0) out_loss[0] = s[0] / (float)NTOK;
}

extern "C" void kernel_launch(void* const* d_in, const int* in_sizes, int n_in,
                              void* d_out, int out_size) {
    const int*   input_ids = (const int*)d_in[0];
    const int*   labels    = (const int*)d_in[3];
    const float* emb_table = (const float*)d_in[4];
    const float* W_h       = (const float*)d_in[5];
    const float* b_h       = (const float*)d_in[6];
    const float* W_out     = (const float*)d_in[7];
    const float* b_out     = (const float*)d_in[8];
    float* out = (float*)d_out;

    // three no-ops so ncu's captured launch (#6, incl. 2 harness launches) = k_precompute
    k_nop<<<1, 32>>>();
    k_nop<<<1, 32>>>();
    k_nop<<<1, 32>>>();
    k_precompute<<<VOCAB / 128, 128>>>(emb_table, W_h, b_h);
    k_scan<<<BATCH, 128>>>(input_ids, W_h);
    k_logits<<<256, 256>>>(labels, W_out, b_out, out);
    k_loss<<<1, 256>>>(out + (out_size - 1), 256);
}

// round 15
// speedup vs baseline: 2.3753x; 1.0058x over previous
#include <cuda_runtime.h>
#include <math.h>

#define VOCAB 32000
#define EMB 128
#define HID 128
#define NLAB 9
#define BATCH 128
#define SEQ 1024
#define NTOK (BATCH * SEQ)
#define BLK 16                     // scan: xw staging block (steps per LDG batch)
#define NBLK (SEQ / BLK)
#define PBURST 8                   // precompute: emb rows staged per barrier

// Scratch (static device arrays: allocation-free, overwrite-only => graph-replay safe)
__device__ float g_T[VOCAB * HID];              // emb_table @ Wx + b_h   (16.4 MB)
__device__ float g_hidden[(size_t)NTOK * HID];  // hidden states (64 MB, streaming)
__device__ float g_partial[512];                // per-CTA loss partials

// ---- packed f32x2 helpers (Blackwell FFMA2) ----
__device__ __forceinline__ unsigned long long pack2(float lo, float hi) {
    unsigned long long r;
    asm("mov.b64 %0, {%1, %2};" : "=l"(r) : "f"(lo), "f"(hi));
    return r;
}
__device__ __forceinline__ unsigned long long fma2(unsigned long long a,
                                                   unsigned long long b,
                                                   unsigned long long c) {
    unsigned long long d;
    asm("fma.rn.f32x2 %0, %1, %2, %3;" : "=l"(d) : "l"(a), "l"(b), "l"(c));
    return d;
}
__device__ __forceinline__ unsigned long long add2(unsigned long long a,
                                                   unsigned long long b) {
    unsigned long long d;
    asm("add.rn.f32x2 %0, %1, %2;" : "=l"(d) : "l"(a), "l"(b));
    return d;
}
__device__ __forceinline__ float sum2(unsigned long long v) {
    float lo, hi;
    asm("mov.b64 {%0, %1}, %2;" : "=f"(lo), "=f"(hi) : "l"(v));
    return lo + hi;
}
__device__ __forceinline__ float tanh_fast(float x) {
    float r;
    asm("tanh.approx.f32 %0, %1;" : "=f"(r) : "f"(x));
    return r;
}
__device__ __forceinline__ void stg_stream(float* p, float v) {
    asm volatile("st.global.cs.f32 [%0], %1;" :: "l"(p), "f"(v));
}

// no-op kernel: shifts ncu's captured launch (4th user launch) onto k_logits
__global__ void k_nop() {}

// ---------------------------------------------------------------------------
// Kernel 1: T[v][j] = sum_e emb[v][e] * Wx[e][j] + b_h[j]
// R15: __launch_bounds__(128, 2) -> reg budget ~256, letting ptxas interleave
// the 8 independent staged rows (cross-row ILP) instead of clamping at 168.
// ---------------------------------------------------------------------------
__global__ void __launch_bounds__(128, 2) k_precompute(const float* __restrict__ emb,
                                                       const float* __restrict__ W_h,
                                                       const float* __restrict__ b_h) {
    const int j = threadIdx.x;
    unsigned long long wx2[EMB / 2];
#pragma unroll
    for (int e = 0; e < EMB / 2; e++)
        wx2[e] = pack2(W_h[(2 * e) * HID + j], W_h[(2 * e + 1) * HID + j]);
    const float bj = b_h[j];

    __shared__ __align__(16) float es[2][PBURST][EMB];
    const int row0 = blockIdx.x * 128;

    // prologue: stage rows 0..7
    {
        float er[PBURST];
#pragma unroll
        for (int u = 0; u < PBURST; u++) er[u] = __ldg(emb + (size_t)(row0 + u) * EMB + j);
#pragma unroll
        for (int u = 0; u < PBURST; u++) es[0][u][j] = er[u];
    }
    __syncthreads();

    const int nblocks = 128 / PBURST;
    for (int blk = 0; blk < nblocks; blk++) {
        const int cur = blk & 1;
        // burst next 8 rows into registers (waited once, at the drain below)
        const int nb = (blk + 1 < nblocks) ? (blk + 1) * PBURST : blk * PBURST;
        float er[PBURST];
#pragma unroll
        for (int u = 0; u < PBURST; u++) er[u] = __ldg(emb + (size_t)(row0 + nb + u) * EMB + j);

#pragma unroll
        for (int u = 0; u < PBURST; u++) {
            const int row = row0 + blk * PBURST + u;
            const ulonglong2* e8 = (const ulonglong2*)es[cur][u];
            unsigned long long a0 = pack2(bj, 0.f), a1 = 0ull, a2 = 0ull, a3 = 0ull;
#pragma unroll
            for (int k = 0; k < EMB / 4; k++) {
                ulonglong2 v = e8[k];
                if ((k & 1) == 0) { a0 = fma2(v.x, wx2[2 * k], a0); a1 = fma2(v.y, wx2[2 * k + 1], a1); }
                else              { a2 = fma2(v.x, wx2[2 * k], a2); a3 = fma2(v.y, wx2[2 * k + 1], a3); }
            }
            g_T[row * HID + j] = sum2(add2(add2(a0, a1), add2(a2, a3)));
        }
        // drain the burst once per 8 rows
#pragma unroll
        for (int u = 0; u < PBURST; u++) es[cur ^ 1][u][j] = er[u];
        __syncthreads();
    }
}

// ---------------------------------------------------------------------------
// Kernel 2: sequential scan — EXACT R9 structure (best measured: 215us).
// UNTOUCHED this round.
// ---------------------------------------------------------------------------
__global__ void __launch_bounds__(128) k_scan(const int* __restrict__ ids,
                                              const float* __restrict__ W_h) {
    const int b = blockIdx.x;
    const int j = threadIdx.x;

    unsigned long long wh2[HID / 2];
#pragma unroll
    for (int k = 0; k < HID / 2; k++)
        wh2[k] = pack2(W_h[(EMB + 2 * k) * HID + j], W_h[(EMB + 2 * k + 1) * HID + j]);

    __shared__ __align__(16) float hs[2][HID];
    __shared__ float xw_sm[2][BLK][HID];   // double-buffered staged gather
    __shared__ int ids_sh[SEQ];
    const int* idrow = ids + b * SEQ;
#pragma unroll
    for (int t = j; t < SEQ; t += 128) ids_sh[t] = idrow[t];
    hs[0][j] = 0.f;
    __syncthreads();

    // prologue: stage block 0
    {
        float xr[BLK];
#pragma unroll
        for (int u = 0; u < BLK; u++) xr[u] = __ldg(g_T + ids_sh[u] * HID + j);
#pragma unroll
        for (int u = 0; u < BLK; u++) xw_sm[0][u][j] = xr[u];
    }
    __syncthreads();

    float* hout = g_hidden + (size_t)b * SEQ * HID + j;
    float prev = 0.f;
    float xr[BLK];

    for (int blk = 0; blk < NBLK; blk++) {
        const int cur = blk & 1;
        // issue next block's gathers NOW; they complete during the 16 steps below
        const int nbase = (blk + 1 < NBLK) ? (blk + 1) * BLK : blk * BLK;
#pragma unroll
        for (int u = 0; u < BLK; u++) xr[u] = __ldg(g_T + ids_sh[nbase + u] * HID + j);

#pragma unroll
        for (int u = 0; u < BLK; u++) {
            const int t = blk * BLK + u;
            const float xw = xw_sm[cur][u][j];          // LDS, 29cyc, no LDG alias

            const int buf = t & 1;
            const ulonglong2* h8 = (const ulonglong2*)hs[buf];
            unsigned long long a0 = pack2(xw, 0.f), a1 = 0ull, a2 = 0ull, a3 = 0ull;
#pragma unroll
            for (int k = 0; k < HID / 4; k++) {
                ulonglong2 v = h8[k];
                if ((k & 1) == 0) { a0 = fma2(v.x, wh2[2 * k], a0); a1 = fma2(v.y, wh2[2 * k + 1], a1); }
                else              { a2 = fma2(v.x, wh2[2 * k], a2); a3 = fma2(v.y, wh2[2 * k + 1], a3); }
            }
            const float hv = tanh_fast(sum2(add2(add2(a0, a1), add2(a2, a3))));
            hs[buf ^ 1][j] = hv;

            if (u == BLK - 1) {
                // drain the block's LDGs ONCE, right before the barrier
#pragma unroll
                for (int v2 = 0; v2 < BLK; v2++) xw_sm[cur ^ 1][v2][j] = xr[v2];
            }
            __syncthreads();
            // store previous h AFTER the barrier: overlaps next step's compute
            if (t) stg_stream(hout + (size_t)(t - 1) * HID, prev);
            prev = hv;
        }
    }
    stg_stream(hout + (size_t)(SEQ - 1) * HID, prev);
}

// ---------------------------------------------------------------------------
// Kernel 3: logits + per-token NLL. One warp per token (strided).
// R15: software-pipelined h loads — token t+1's four vectors are issued
// before token t's compute, hiding the ~500cyc memory latency behind the
// FMA + shuffle work of the current token.
// ---------------------------------------------------------------------------
__global__ void __launch_bounds__(256) k_logits(const int* __restrict__ labels,
                                                const float* __restrict__ W_out,
                                                const float* __restrict__ b_out,
                                                float* __restrict__ out_logits) {
    __shared__ float Wsh[HID * NLAB];
    __shared__ float bsh[NLAB];
    __shared__ float wsum[8];
    const int tid = threadIdx.x;
    for (int i = tid; i < HID * NLAB; i += blockDim.x) Wsh[i] = W_out[i];
    if (tid < NLAB) bsh[tid] = b_out[tid];
    __syncthreads();

    const int lane = tid & 31, warp = tid >> 5;
    const int gwarp = blockIdx.x * (blockDim.x >> 5) + warp;
    const int nwarp = gridDim.x * (blockDim.x >> 5);
    float lsum = 0.f;

    // prologue: load first token's h
    float h0 = 0.f, h1 = 0.f, h2 = 0.f, h3 = 0.f;
    if (gwarp < NTOK) {
        const float* h = g_hidden + (size_t)gwarp * HID;
        h0 = __ldcs(h + lane); h1 = __ldcs(h + lane + 32);
        h2 = __ldcs(h + lane + 64); h3 = __ldcs(h + lane + 96);
    }

    for (int tok = gwarp; tok < NTOK; tok += nwarp) {
        // issue next token's loads NOW (complete during this token's compute)
        const int tnext = tok + nwarp;
        float n0 = 0.f, n1 = 0.f, n2 = 0.f, n3 = 0.f;
        if (tnext < NTOK) {
            const float* hn = g_hidden + (size_t)tnext * HID;
            n0 = __ldcs(hn + lane); n1 = __ldcs(hn + lane + 32);
            n2 = __ldcs(hn + lane + 64); n3 = __ldcs(hn + lane + 96);
        }

        float lg[NLAB];
#pragma unroll
        for (int l = 0; l < NLAB; l++) {
            float p = h0 * Wsh[lane * NLAB + l]
                    + h1 * Wsh[(lane + 32) * NLAB + l]
                    + h2 * Wsh[(lane + 64) * NLAB + l]
                    + h3 * Wsh[(lane + 96) * NLAB + l];
#pragma unroll
            for (int off = 16; off; off >>= 1) p += __shfl_xor_sync(0xffffffffu, p, off);
            lg[l] = p + bsh[l];
        }
        if (lane < NLAB) stg_stream(out_logits + (size_t)tok * NLAB + lane, lg[lane]);
        if (lane == 0) {
            float m = lg[0];
#pragma unroll
            for (int l = 1; l < NLAB; l++) m = fmaxf(m, lg[l]);
            float s = 0.f;
#pragma unroll
            for (int l = 0; l < NLAB; l++) s += expf(lg[l] - m);
            const float lse = m + logf(s);
            lsum += lse - lg[labels[tok]];
        }
        h0 = n0; h1 = n1; h2 = n2; h3 = n3;
    }
    if (lane == 0) wsum[warp] = lsum;
    __syncthreads();
    if (tid == 0) {
        float s = 0.f;
#pragma unroll
        for (int w = 0; w < 8; w++) s += wsum[w];
        g_partial[blockIdx.x] = s;  // overwrite, replay-safe
    }
}

// ---------------------------------------------------------------------------
// Kernel 4: reduce partials -> loss scalar
// ---------------------------------------------------------------------------
__global__ void __launch_bounds__(256) k_loss(float* __restrict__ out_loss, int nblocks) {
    __shared__ float s[256];
    float v = 0.f;
    for (int i = threadIdx.x; i < nblocks; i += 256) v += g_partial[i];
    s[threadIdx.x] = v;
    __syncthreads();
    for (int st = 128; st; st >>= 1) {
        if (threadIdx.x < st) s[threadIdx.x] += s[threadIdx.x + st];
        __syncthreads();
    }
    if (threadIdx.x == 0) out_loss[0] = s[0] / (float)NTOK;
}

extern "C" void kernel_launch(void* const* d_in, const int* in_sizes, int n_in,
                              void* d_out, int out_size) {
    const int*   input_ids = (const int*)d_in[0];
    const int*   labels    = (const int*)d_in[3];
    const float* emb_table = (const float*)d_in[4];
    const float* W_h       = (const float*)d_in[5];
    const float* b_h       = (const float*)d_in[6];
    const float* W_out     = (const float*)d_in[7];
    const float* b_out     = (const float*)d_in[8];
    float* out = (float*)d_out;

    // one no-op: ncu's captured (4th user) launch = k_logits this round
    k_nop<<<1, 32>>>();
    k_precompute<<<VOCAB / 128, 128>>>(emb_table, W_h, b_h);
    k_scan<<<BATCH, 128>>>(input_ids, W_h);
    k_logits<<<256, 256>>>(labels, W_out, b_out, out);
    k_loss<<<1, 256>>>(out + (out_size - 1), 256);
}

// round 16
// speedup vs baseline: 2.5092x; 1.0564x over previous
#include <cuda_runtime.h>
#include <math.h>

#define VOCAB 32000
#define EMB 128
#define HID 128
#define NLAB 9
#define BATCH 128
#define SEQ 1024
#define NTOK (BATCH * SEQ)
#define BLK 16                     // scan: xw staging block (steps per LDG batch)
#define NBLK (SEQ / BLK)
#define PBURST 8                   // precompute: emb rows staged per barrier
#define LOGITS_GRID 512

// Scratch (static device arrays: allocation-free, overwrite-only => graph-replay safe)
__device__ float g_T[VOCAB * HID];              // emb_table @ Wx + b_h   (16.4 MB)
__device__ float g_hidden[(size_t)NTOK * HID];  // hidden states (64 MB, streaming)
__device__ float g_partial[512];                // per-CTA loss partials

// ---- packed f32x2 helpers (Blackwell FFMA2) ----
__device__ __forceinline__ unsigned long long pack2(float lo, float hi) {
    unsigned long long r;
    asm("mov.b64 %0, {%1, %2};" : "=l"(r) : "f"(lo), "f"(hi));
    return r;
}
__device__ __forceinline__ unsigned long long fma2(unsigned long long a,
                                                   unsigned long long b,
                                                   unsigned long long c) {
    unsigned long long d;
    asm("fma.rn.f32x2 %0, %1, %2, %3;" : "=l"(d) : "l"(a), "l"(b), "l"(c));
    return d;
}
__device__ __forceinline__ unsigned long long add2(unsigned long long a,
                                                   unsigned long long b) {
    unsigned long long d;
    asm("add.rn.f32x2 %0, %1, %2;" : "=l"(d) : "l"(a), "l"(b));
    return d;
}
__device__ __forceinline__ float sum2(unsigned long long v) {
    float lo, hi;
    asm("mov.b64 {%0, %1}, %2;" : "=f"(lo), "=f"(hi) : "l"(v));
    return lo + hi;
}
__device__ __forceinline__ float tanh_fast(float x) {
    float r;
    asm("tanh.approx.f32 %0, %1;" : "=f"(r) : "f"(x));
    return r;
}
__device__ __forceinline__ void stg_stream(float* p, float v) {
    asm volatile("st.global.cs.f32 [%0], %1;" :: "l"(p), "f"(v));
}

// no-op kernel: shifts ncu's captured launch (4th user launch) onto k_logits
__global__ void k_nop() {}

// ---------------------------------------------------------------------------
// Kernel 1: T[v][j] = sum_e emb[v][e] * Wx[e][j] + b_h[j]   (R14 structure)
// ---------------------------------------------------------------------------
__global__ void __launch_bounds__(128, 2) k_precompute(const float* __restrict__ emb,
                                                       const float* __restrict__ W_h,
                                                       const float* __restrict__ b_h) {
    const int j = threadIdx.x;
    unsigned long long wx2[EMB / 2];
#pragma unroll
    for (int e = 0; e < EMB / 2; e++)
        wx2[e] = pack2(W_h[(2 * e) * HID + j], W_h[(2 * e + 1) * HID + j]);
    const float bj = b_h[j];

    __shared__ __align__(16) float es[2][PBURST][EMB];
    const int row0 = blockIdx.x * 128;

    // prologue: stage rows 0..7
    {
        float er[PBURST];
#pragma unroll
        for (int u = 0; u < PBURST; u++) er[u] = __ldg(emb + (size_t)(row0 + u) * EMB + j);
#pragma unroll
        for (int u = 0; u < PBURST; u++) es[0][u][j] = er[u];
    }
    __syncthreads();

    const int nblocks = 128 / PBURST;
    for (int blk = 0; blk < nblocks; blk++) {
        const int cur = blk & 1;
        const int nb = (blk + 1 < nblocks) ? (blk + 1) * PBURST : blk * PBURST;
        float er[PBURST];
#pragma unroll
        for (int u = 0; u < PBURST; u++) er[u] = __ldg(emb + (size_t)(row0 + nb + u) * EMB + j);

#pragma unroll
        for (int u = 0; u < PBURST; u++) {
            const int row = row0 + blk * PBURST + u;
            const ulonglong2* e8 = (const ulonglong2*)es[cur][u];
            unsigned long long a0 = pack2(bj, 0.f), a1 = 0ull, a2 = 0ull, a3 = 0ull;
#pragma unroll
            for (int k = 0; k < EMB / 4; k++) {
                ulonglong2 v = e8[k];
                if ((k & 1) == 0) { a0 = fma2(v.x, wx2[2 * k], a0); a1 = fma2(v.y, wx2[2 * k + 1], a1); }
                else              { a2 = fma2(v.x, wx2[2 * k], a2); a3 = fma2(v.y, wx2[2 * k + 1], a3); }
            }
            g_T[row * HID + j] = sum2(add2(add2(a0, a1), add2(a2, a3)));
        }
#pragma unroll
        for (int u = 0; u < PBURST; u++) es[cur ^ 1][u][j] = er[u];
        __syncthreads();
    }
}

// ---------------------------------------------------------------------------
// Kernel 2: sequential scan — EXACT R9 structure (best measured: 215us).
// UNTOUCHED.
// ---------------------------------------------------------------------------
__global__ void __launch_bounds__(128) k_scan(const int* __restrict__ ids,
                                              const float* __restrict__ W_h) {
    const int b = blockIdx.x;
    const int j = threadIdx.x;

    unsigned long long wh2[HID / 2];
#pragma unroll
    for (int k = 0; k < HID / 2; k++)
        wh2[k] = pack2(W_h[(EMB + 2 * k) * HID + j], W_h[(EMB + 2 * k + 1) * HID + j]);

    __shared__ __align__(16) float hs[2][HID];
    __shared__ float xw_sm[2][BLK][HID];   // double-buffered staged gather
    __shared__ int ids_sh[SEQ];
    const int* idrow = ids + b * SEQ;
#pragma unroll
    for (int t = j; t < SEQ; t += 128) ids_sh[t] = idrow[t];
    hs[0][j] = 0.f;
    __syncthreads();

    // prologue: stage block 0
    {
        float xr[BLK];
#pragma unroll
        for (int u = 0; u < BLK; u++) xr[u] = __ldg(g_T + ids_sh[u] * HID + j);
#pragma unroll
        for (int u = 0; u < BLK; u++) xw_sm[0][u][j] = xr[u];
    }
    __syncthreads();

    float* hout = g_hidden + (size_t)b * SEQ * HID + j;
    float prev = 0.f;
    float xr[BLK];

    for (int blk = 0; blk < NBLK; blk++) {
        const int cur = blk & 1;
        const int nbase = (blk + 1 < NBLK) ? (blk + 1) * BLK : blk * BLK;
#pragma unroll
        for (int u = 0; u < BLK; u++) xr[u] = __ldg(g_T + ids_sh[nbase + u] * HID + j);

#pragma unroll
        for (int u = 0; u < BLK; u++) {
            const int t = blk * BLK + u;
            const float xw = xw_sm[cur][u][j];          // LDS, 29cyc, no LDG alias

            const int buf = t & 1;
            const ulonglong2* h8 = (const ulonglong2*)hs[buf];
            unsigned long long a0 = pack2(xw, 0.f), a1 = 0ull, a2 = 0ull, a3 = 0ull;
#pragma unroll
            for (int k = 0; k < HID / 4; k++) {
                ulonglong2 v = h8[k];
                if ((k & 1) == 0) { a0 = fma2(v.x, wh2[2 * k], a0); a1 = fma2(v.y, wh2[2 * k + 1], a1); }
                else              { a2 = fma2(v.x, wh2[2 * k], a2); a3 = fma2(v.y, wh2[2 * k + 1], a3); }
            }
            const float hv = tanh_fast(sum2(add2(add2(a0, a1), add2(a2, a3))));
            hs[buf ^ 1][j] = hv;

            if (u == BLK - 1) {
#pragma unroll
                for (int v2 = 0; v2 < BLK; v2++) xw_sm[cur ^ 1][v2][j] = xr[v2];
            }
            __syncthreads();
            if (t) stg_stream(hout + (size_t)(t - 1) * HID, prev);
            prev = hv;
        }
    }
    stg_stream(hout + (size_t)(SEQ - 1) * HID, prev);
}

// ---------------------------------------------------------------------------
// Kernel 3: logits + per-token NLL. One warp per token (strided).
// R16: (a) W_out hoisted into 36 loop-invariant REGISTERS (the old code
// re-read 36 SMEM values per token — regs=40 proved ptxas didn't hoist);
// (b) grid 256 -> 512 for ~2x warps/SM to hide the SHFL chains.
// ---------------------------------------------------------------------------
__global__ void __launch_bounds__(256) k_logits(const int* __restrict__ labels,
                                                const float* __restrict__ W_out,
                                                const float* __restrict__ b_out,
                                                float* __restrict__ out_logits) {
    __shared__ float Wsh[HID * NLAB];
    __shared__ float bsh[NLAB];
    __shared__ float wsum[8];
    const int tid = threadIdx.x;
    for (int i = tid; i < HID * NLAB; i += blockDim.x) Wsh[i] = W_out[i];
    if (tid < NLAB) bsh[tid] = b_out[tid];
    __syncthreads();

    const int lane = tid & 31, warp = tid >> 5;
    const int gwarp = blockIdx.x * (blockDim.x >> 5) + warp;
    const int nwarp = gridDim.x * (blockDim.x >> 5);

    // hoist this lane's 36 W values into registers (loop-invariant)
    float wr[4][NLAB];
#pragma unroll
    for (int i = 0; i < 4; i++)
#pragma unroll
        for (int l = 0; l < NLAB; l++)
            wr[i][l] = Wsh[(lane + 32 * i) * NLAB + l];
    float br[NLAB];
#pragma unroll
    for (int l = 0; l < NLAB; l++) br[l] = bsh[l];

    float lsum = 0.f;

    // prologue: load first token's h
    float h0 = 0.f, h1 = 0.f, h2 = 0.f, h3 = 0.f;
    if (gwarp < NTOK) {
        const float* h = g_hidden + (size_t)gwarp * HID;
        h0 = __ldcs(h + lane); h1 = __ldcs(h + lane + 32);
        h2 = __ldcs(h + lane + 64); h3 = __ldcs(h + lane + 96);
    }

    for (int tok = gwarp; tok < NTOK; tok += nwarp) {
        const int tnext = tok + nwarp;
        float n0 = 0.f, n1 = 0.f, n2 = 0.f, n3 = 0.f;
        if (tnext < NTOK) {
            const float* hn = g_hidden + (size_t)tnext * HID;
            n0 = __ldcs(hn + lane); n1 = __ldcs(hn + lane + 32);
            n2 = __ldcs(hn + lane + 64); n3 = __ldcs(hn + lane + 96);
        }

        float lg[NLAB];
#pragma unroll
        for (int l = 0; l < NLAB; l++) {
            float p = h0 * wr[0][l] + h1 * wr[1][l] + h2 * wr[2][l] + h3 * wr[3][l];
#pragma unroll
            for (int off = 16; off; off >>= 1) p += __shfl_xor_sync(0xffffffffu, p, off);
            lg[l] = p + br[l];
        }
        if (lane < NLAB) stg_stream(out_logits + (size_t)tok * NLAB + lane, lg[lane]);
        if (lane == 0) {
            float m = lg[0];
#pragma unroll
            for (int l = 1; l < NLAB; l++) m = fmaxf(m, lg[l]);
            float s = 0.f;
#pragma unroll
            for (int l = 0; l < NLAB; l++) s += expf(lg[l] - m);
            const float lse = m + logf(s);
            lsum += lse - lg[labels[tok]];
        }
        h0 = n0; h1 = n1; h2 = n2; h3 = n3;
    }
    if (lane == 0) wsum[warp] = lsum;
    __syncthreads();
    if (tid == 0) {
        float s = 0.f;
#pragma unroll
        for (int w = 0; w < 8; w++) s += wsum[w];
        g_partial[blockIdx.x] = s;  // overwrite, replay-safe
    }
}

// ---------------------------------------------------------------------------
// Kernel 4: reduce partials -> loss scalar
// ---------------------------------------------------------------------------
__global__ void __launch_bounds__(256) k_loss(float* __restrict__ out_loss, int nblocks) {
    __shared__ float s[256];
    float v = 0.f;
    for (int i = threadIdx.x; i < nblocks; i += 256) v += g_partial[i];
    s[threadIdx.x] = v;
    __syncthreads();
    for (int st = 128; st; st >>= 1) {
        if (threadIdx.x < st) s[threadIdx.x] += s[threadIdx.x + st];
        __syncthreads();
    }
    if (threadIdx.x == 0) out_loss[0] = s[0] / (float)NTOK;
}

extern "C" void kernel_launch(void* const* d_in, const int* in_sizes, int n_in,
                              void* d_out, int out_size) {
    const int*   input_ids = (const int*)d_in[0];
    const int*   labels    = (const int*)d_in[3];
    const float* emb_table = (const float*)d_in[4];
    const float* W_h       = (const float*)d_in[5];
    const float* b_h       = (const float*)d_in[6];
    const float* W_out     = (const float*)d_in[7];
    const float* b_out     = (const float*)d_in[8];
    float* out = (float*)d_out;

    // one no-op: ncu's captured (4th user) launch = k_logits this round
    k_nop<<<1, 32>>>();
    k_precompute<<<VOCAB / 128, 128>>>(emb_table, W_h, b_h);
    k_scan<<<BATCH, 128>>>(input_ids, W_h);
    k_logits<<<LOGITS_GRID, 256>>>(labels, W_out, b_out, out);
    k_loss<<<1, 256>>>(out + (out_size - 1), LOGITS_GRID);
}